// round 5
// baseline (speedup 1.0000x reference)
#include <cuda_runtime.h>

#define T_DIM 4096
#define K_DIM 16384
#define HCN 4
#define N_OUT 24
#define NP 12          // float2 pairs across N
#define MB 32          // rows per CTA
#define KSPLIT 8
#define KCHUNK (K_DIM / KSPLIT)   // 2048
#define KT 512         // K tile staged in smem
#define NTILES (KCHUNK / KT)      // 4
#define BIGS (KT / 64)            // 8 big-iters per tile
#define TOTBIG (NTILES * BIGS)    // 32 big-iters per chunk
#define RT 2           // rows per warp
#define NTHREADS 512
#define PPAD 13        // padded pair stride for reduction

// Scratch (device globals). Transposed [split][pair][row] for coalesced reads.
__device__ float2 g_hpart[KSPLIT][NP][T_DIM];
__device__ float  g_sspart[KSPLIT][T_DIM];

using u64 = unsigned long long;

__device__ __forceinline__ u64 fma2(u64 a, u64 b, u64 c) {
    u64 d;
    asm("fma.rn.f32x2 %0, %1, %2, %3;" : "=l"(d) : "l"(a), "l"(b), "l"(c));
    return d;
}
__device__ __forceinline__ u64 pack2(float x) {
    u64 d;
    asm("mov.b64 %0, {%1, %1};" : "=l"(d) : "f"(x));
    return d;
}
__device__ __forceinline__ float2 u2f(u64 a) {
    float2 f;
    asm("mov.b64 {%0, %1}, %2;" : "=f"(f.x), "=f"(f.y) : "l"(a));
    return f;
}
__device__ __forceinline__ float frcp(float a) {
    float r;
    asm("rcp.approx.f32 %0, %1;" : "=f"(r) : "f"(a));
    return r;
}
__device__ __forceinline__ float f4get(const float4& v, int s) {
    return s == 0 ? v.x : (s == 1 ? v.y : (s == 2 ? v.z : v.w));
}

// ---------------------------------------------------------------------------
// Kernel A. Warp layout: lane = half*16 + kth. Each warp owns RT=2 rows;
// lanes 0-15 accumulate pairs 0-5, lanes 16-31 pairs 6-11 (same rows/k).
// 512 threads, ~80 regs/thread, 1 CTA/SM -> 4 warps/SMSP, NO spills.
// x prefetched one 64-k big-iter ahead.
// ---------------------------------------------------------------------------
extern "C" __global__ void __launch_bounds__(NTHREADS, 1)
mhc_gemm_kernel(const float* __restrict__ x, const float* __restrict__ w) {
    extern __shared__ char smem[];
    u64* sw = (u64*)smem;  // [NP][4 phases][KT/4] u64 (float2 pairs)

    const int tid = threadIdx.x;
    const int wid = tid >> 5;          // warp 0..15
    const int half = (tid >> 4) & 1;   // N-half
    const int kth = tid & 15;          // k lane
    const int p6 = half * 6;
    const int bm = blockIdx.x;
    const int bk = blockIdx.y;
    const int row0 = bm * MB;
    const int rbase = row0 + wid * RT;

    const float4* xb0 = (const float4*)(x + (size_t)(rbase + 0) * K_DIM) + bk * (KCHUNK / 4);
    const float4* xb1 = (const float4*)(x + (size_t)(rbase + 1) * K_DIM) + bk * (KCHUNK / 4);

    u64 acc[RT][6];
    float ss0 = 0.f, ss1 = 0.f;
#pragma unroll
    for (int r = 0; r < RT; r++)
#pragma unroll
        for (int p = 0; p < 6; p++) acc[r][p] = 0ull;

    // Prefetch first big-iter
    float4 n0 = __ldcs(xb0 + kth);
    float4 n1 = __ldcs(xb1 + kth);

    for (int tile = 0; tile < NTILES; tile++) {
        const int k0 = bk * KCHUNK + tile * KT;

        // Stage W[k0..k0+KT)[0:24) -> sw[pair][k&3][k>>2]; 6 iters @512 thr
#pragma unroll
        for (int it = 0; it < (KT * 6) / NTHREADS; it++) {
            int idx = tid + NTHREADS * it;
            int kk = idx / 6, q = idx % 6;
            float4 v = *(const float4*)(w + (size_t)(k0 + kk) * N_OUT + q * 4);
            int base = (kk & 3) * (KT / 4) + (kk >> 2);
            ((float2*)sw)[(2 * q + 0) * KT + base] = make_float2(v.x, v.y);
            ((float2*)sw)[(2 * q + 1) * KT + base] = make_float2(v.z, v.w);
        }
        __syncthreads();

        for (int i = 0; i < BIGS; i++) {
            float4 c0 = n0, c1 = n1;
            int gnext = tile * BIGS + i + 1;
            if (gnext > TOTBIG - 1) gnext = TOTBIG - 1;
            n0 = __ldcs(xb0 + gnext * 16 + kth);
            n1 = __ldcs(xb1 + gnext * 16 + kth);

            const int kf4 = i * 16 + kth;   // float4 index within tile
#pragma unroll
            for (int s = 0; s < 4; s++) {
                u64 wp[6];
#pragma unroll
                for (int p = 0; p < 6; p++)
                    wp[p] = sw[(p6 + p) * KT + s * (KT / 4) + kf4];
                float xs0 = f4get(c0, s), xs1 = f4get(c1, s);
                u64 X0 = pack2(xs0), X1 = pack2(xs1);
#pragma unroll
                for (int p = 0; p < 6; p++) {
                    acc[0][p] = fma2(X0, wp[p], acc[0][p]);
                    acc[1][p] = fma2(X1, wp[p], acc[1][p]);
                }
                ss0 = fmaf(xs0, xs0, ss0);
                ss1 = fmaf(xs1, xs1, ss1);
            }
        }
        __syncthreads();
    }

    // Cross-kth reduction via smem (overlays weight buffer).
    float2* red = (float2*)smem;                                  // [32][16][PPAD]
    float* ssred = (float*)(smem + (size_t)MB * 16 * PPAD * 8);   // [32][16]
    {
        float ssl[RT] = {ss0, ss1};
#pragma unroll
        for (int r = 0; r < RT; r++) {
            int rl = wid * RT + r;
#pragma unroll
            for (int p = 0; p < 6; p++)
                red[((size_t)rl * 16 + kth) * PPAD + p6 + p] = u2f(acc[r][p]);
            if (half == 0) ssred[rl * 16 + kth] = ssl[r];
        }
    }
    __syncthreads();

    // 32 rows x 12 pairs = 384 columns; one per thread
    if (tid < MB * NP) {
        int p = tid >> 5, rl = tid & 31;   // lanes consecutive in rl -> coalesced out
        float sx = 0.f, sy = 0.f;
#pragma unroll
        for (int t = 0; t < 16; t++) {
            float2 a = red[((size_t)rl * 16 + t) * PPAD + p];
            sx += a.x;
            sy += a.y;
        }
        g_hpart[bk][p][row0 + rl] = make_float2(sx, sy);
    }
    if (tid < MB) {
        float s = 0.f;
#pragma unroll
        for (int t = 0; t < 16; t++) s += ssred[tid * 16 + t];
        g_sspart[bk][row0 + tid] = s;
    }
}

// ---------------------------------------------------------------------------
// Kernel B: two rows per thread, interleaved Sinkhorn chains (fills the
// per-iteration dependency bubbles). rcp.approx only; convergence checked
// every 8 iterations via multiply-compare. Cap 400 = reference MAX_IT^2.
// ---------------------------------------------------------------------------
extern "C" __global__ void __launch_bounds__(32)
mhc_finish_kernel(const float* __restrict__ bias, const float* __restrict__ alpha,
                  float* __restrict__ out) {
    const int rowA = blockIdx.x * 64 + threadIdx.x;
    const int rowB = rowA + 32;

    float hA[N_OUT], hB[N_OUT];
#pragma unroll
    for (int p = 0; p < NP; p++) {
        float ax = 0.f, ay = 0.f, bx = 0.f, by = 0.f;
#pragma unroll
        for (int c = 0; c < KSPLIT; c++) {
            float2 a = g_hpart[c][p][rowA];
            float2 b = g_hpart[c][p][rowB];
            ax += a.x; ay += a.y;
            bx += b.x; by += b.y;
        }
        hA[2 * p] = ax; hA[2 * p + 1] = ay;
        hB[2 * p] = bx; hB[2 * p + 1] = by;
    }
    float ssA = 0.f, ssB = 0.f;
#pragma unroll
    for (int c = 0; c < KSPLIT; c++) {
        ssA += g_sspart[c][rowA];
        ssB += g_sspart[c][rowB];
    }

    float riA = rsqrtf(ssA * (1.0f / K_DIM));
    float riB = rsqrtf(ssB * (1.0f / K_DIM));
    float a0 = alpha[0], a1 = alpha[1], a2 = alpha[2];

    float preA[HCN], postA[HCN], HA[HCN][HCN];
    float preB[HCN], postB[HCN], HB[HCN][HCN];
#pragma unroll
    for (int n = 0; n < HCN; n++) {
        float b0 = bias[n], b1 = bias[HCN + n];
        preA[n] = 1.f / (1.f + __expf(-fmaf(riA * a0, hA[n], b0)));
        preB[n] = 1.f / (1.f + __expf(-fmaf(riB * a0, hB[n], b0)));
        postA[n] = 2.f / (1.f + __expf(-fmaf(riA * a1, hA[HCN + n], b1)));
        postB[n] = 2.f / (1.f + __expf(-fmaf(riB * a1, hB[HCN + n], b1)));
    }
#pragma unroll
    for (int i = 0; i < HCN; i++)
#pragma unroll
        for (int j = 0; j < HCN; j++) {
            float bb = bias[8 + 4 * i + j];
            HA[i][j] = __expf(fmaf(riA * a2, hA[8 + 4 * i + j], bb));
            HB[i][j] = __expf(fmaf(riB * a2, hB[8 + 4 * i + j], bb));
        }

    const float EPSV = 1e-12f;
    float uA[4] = {1.f, 1.f, 1.f, 1.f}, vA[4] = {1.f, 1.f, 1.f, 1.f};
    float uB[4] = {1.f, 1.f, 1.f, 1.f}, vB[4] = {1.f, 1.f, 1.f, 1.f};
    for (int o = 0; o < 50; o++) {          // 50 blocks x 8 iters = 400 max
        float pA0 = vA[0], pA1 = vA[1], pA2 = vA[2], pA3 = vA[3];
        float pB0 = vB[0], pB1 = vB[1], pB2 = vB[2], pB3 = vB[3];
#pragma unroll
        for (int s = 0; s < 8; s++) {
            float nuA[4], nuB[4];
#pragma unroll
            for (int i = 0; i < 4; i++) {
                float da = fmaf(HA[i][3], vA[3], fmaf(HA[i][2], vA[2],
                           fmaf(HA[i][1], vA[1], fmaf(HA[i][0], vA[0], EPSV))));
                float db = fmaf(HB[i][3], vB[3], fmaf(HB[i][2], vB[2],
                           fmaf(HB[i][1], vB[1], fmaf(HB[i][0], vB[0], EPSV))));
                nuA[i] = frcp(da);
                nuB[i] = frcp(db);
            }
#pragma unroll
            for (int j = 0; j < 4; j++) {
                float da = fmaf(HA[3][j], nuA[3], fmaf(HA[2][j], nuA[2],
                           fmaf(HA[1][j], nuA[1], fmaf(HA[0][j], nuA[0], EPSV))));
                float db = fmaf(HB[3][j], nuB[3], fmaf(HB[2][j], nuB[2],
                           fmaf(HB[1][j], nuB[1], fmaf(HB[0][j], nuB[0], EPSV))));
                vA[j] = frcp(da);
                vB[j] = frcp(db);
            }
#pragma unroll
            for (int i = 0; i < 4; i++) { uA[i] = nuA[i]; uB[i] = nuB[i]; }
        }
        float m = fabsf(vA[0] - pA0) - 1e-6f * fabsf(vA[0]);
        m = fmaxf(m, fabsf(vA[1] - pA1) - 1e-6f * fabsf(vA[1]));
        m = fmaxf(m, fabsf(vA[2] - pA2) - 1e-6f * fabsf(vA[2]));
        m = fmaxf(m, fabsf(vA[3] - pA3) - 1e-6f * fabsf(vA[3]));
        m = fmaxf(m, fabsf(vB[0] - pB0) - 1e-6f * fabsf(vB[0]));
        m = fmaxf(m, fabsf(vB[1] - pB1) - 1e-6f * fabsf(vB[1]));
        m = fmaxf(m, fabsf(vB[2] - pB2) - 1e-6f * fabsf(vB[2]));
        m = fmaxf(m, fabsf(vB[3] - pB3) - 1e-6f * fabsf(vB[3]));
        if (m <= 0.f) break;
    }

    // Outputs: [h_pre (T,4)] [h_post (T,4)] [h_res (T,4,4)], float4 stores
    ((float4*)out)[rowA] = make_float4(preA[0], preA[1], preA[2], preA[3]);
    ((float4*)out)[rowB] = make_float4(preB[0], preB[1], preB[2], preB[3]);
    ((float4*)(out + (size_t)T_DIM * HCN))[rowA] =
        make_float4(postA[0], postA[1], postA[2], postA[3]);
    ((float4*)(out + (size_t)T_DIM * HCN))[rowB] =
        make_float4(postB[0], postB[1], postB[2], postB[3]);
    float4* resA = (float4*)(out + 2 * (size_t)T_DIM * HCN + (size_t)rowA * 16);
    float4* resB = (float4*)(out + 2 * (size_t)T_DIM * HCN + (size_t)rowB * 16);
#pragma unroll
    for (int i = 0; i < 4; i++) {
        resA[i] = make_float4(uA[i] * HA[i][0] * vA[0], uA[i] * HA[i][1] * vA[1],
                              uA[i] * HA[i][2] * vA[2], uA[i] * HA[i][3] * vA[3]);
        resB[i] = make_float4(uB[i] * HB[i][0] * vB[0], uB[i] * HB[i][1] * vB[1],
                              uB[i] * HB[i][2] * vB[2], uB[i] * HB[i][3] * vB[3]);
    }
}

// ---------------------------------------------------------------------------
// smem: max(staging 12*KT*8 = 49152, reduction 32*16*13*8 + 32*16*4 = 55296)
#define SMEM_BYTES 55296

extern "C" void kernel_launch(void* const* d_in, const int* in_sizes, int n_in,
                              void* d_out, int out_size) {
    const float* x = (const float*)d_in[0];
    const float* w = (const float*)d_in[1];
    const float* bias = (const float*)d_in[2];
    const float* alpha = (const float*)d_in[3];
    float* out = (float*)d_out;

    cudaFuncSetAttribute(mhc_gemm_kernel,
                         cudaFuncAttributeMaxDynamicSharedMemorySize,
                         SMEM_BYTES);

    dim3 grid(T_DIM / MB, KSPLIT);
    mhc_gemm_kernel<<<grid, NTHREADS, SMEM_BYTES>>>(x, w);
    mhc_finish_kernel<<<T_DIM / 64, 32>>>(bias, alpha, out);
}

// round 6
// speedup vs baseline: 1.2860x; 1.2860x over previous
#include <cuda_runtime.h>

#define T_DIM 4096
#define K_DIM 16384
#define HCN 4
#define N_OUT 24
#define NP 12          // float2 pairs across N
#define MB 32          // rows per CTA
#define KSPLIT 8
#define KCHUNK (K_DIM / KSPLIT)   // 2048
#define KT 512         // K tile staged in smem
#define NTILES (KCHUNK / KT)      // 4
#define BIGS (KT / 64)            // 8 big-iters (64 k) per tile
#define TOTBIG (NTILES * BIGS)    // 32 big-iters per chunk
#define RT 4           // rows per warp
#define DEPTH 4        // x prefetch ring depth (16 LDG.128 in flight / warp)
#define NTHREADS 256
#define PPAD 13        // padded pair stride for reduction

// Scratch (device globals). Transposed [split][pair][row] for coalesced reads.
__device__ float2 g_hpart[KSPLIT][NP][T_DIM];
__device__ float  g_sspart[KSPLIT][T_DIM];

using u64 = unsigned long long;

__device__ __forceinline__ u64 fma2(u64 a, u64 b, u64 c) {
    u64 d;
    asm("fma.rn.f32x2 %0, %1, %2, %3;" : "=l"(d) : "l"(a), "l"(b), "l"(c));
    return d;
}
__device__ __forceinline__ u64 pack2(float x) {
    u64 d;
    asm("mov.b64 %0, {%1, %1};" : "=l"(d) : "f"(x));
    return d;
}
__device__ __forceinline__ float2 u2f(u64 a) {
    float2 f;
    asm("mov.b64 {%0, %1}, %2;" : "=f"(f.x), "=f"(f.y) : "l"(a));
    return f;
}
__device__ __forceinline__ float frcp(float a) {
    float r;
    asm("rcp.approx.f32 %0, %1;" : "=f"(r) : "f"(a));
    return r;
}
__device__ __forceinline__ float f4get(const float4& v, int s) {
    return s == 0 ? v.x : (s == 1 ? v.y : (s == 2 ? v.z : v.w));
}

// ---------------------------------------------------------------------------
// Kernel A. Warp layout: lane = half*16 + kth. Each warp owns RT=4 rows;
// lanes 0-15 accumulate pairs 0-5, lanes 16-31 pairs 6-11 (same rows, same k;
// duplicate x addresses across halves dedup in L1 within the warp-inst).
// Depth-4 register prefetch ring: 16 outstanding LDG.128 per warp to push
// the DRAM stream from latency-limited ~1.25 TB/s toward >4 TB/s.
// ---------------------------------------------------------------------------
extern "C" __global__ void __launch_bounds__(NTHREADS, 1)
mhc_gemm_kernel(const float* __restrict__ x, const float* __restrict__ w) {
    extern __shared__ char smem[];
    u64* sw = (u64*)smem;  // [NP][4 phases][KT/4] u64 (float2 pairs)

    const int tid = threadIdx.x;
    const int wid = tid >> 5;          // warp 0..7
    const int half = (tid >> 4) & 1;   // N-half
    const int kth = tid & 15;          // k lane
    const int p6 = half * 6;
    const int bm = blockIdx.x;
    const int bk = blockIdx.y;
    const int row0 = bm * MB;
    const int rbase = row0 + wid * RT;

    const float4* xb0 = (const float4*)(x + (size_t)(rbase + 0) * K_DIM) + bk * (KCHUNK / 4);
    const float4* xb1 = (const float4*)(x + (size_t)(rbase + 1) * K_DIM) + bk * (KCHUNK / 4);
    const float4* xb2 = (const float4*)(x + (size_t)(rbase + 2) * K_DIM) + bk * (KCHUNK / 4);
    const float4* xb3 = (const float4*)(x + (size_t)(rbase + 3) * K_DIM) + bk * (KCHUNK / 4);

    u64 acc[RT][6];
    float ss0 = 0.f, ss1 = 0.f, ss2 = 0.f, ss3 = 0.f;
#pragma unroll
    for (int r = 0; r < RT; r++)
#pragma unroll
        for (int p = 0; p < 6; p++) acc[r][p] = 0ull;

    // Preload prefetch ring: big-iters 0..DEPTH-1
    float4 ring[DEPTH][RT];
#pragma unroll
    for (int st = 0; st < DEPTH; st++) {
        int off = st * 16 + kth;
        ring[st][0] = __ldcs(xb0 + off);
        ring[st][1] = __ldcs(xb1 + off);
        ring[st][2] = __ldcs(xb2 + off);
        ring[st][3] = __ldcs(xb3 + off);
    }

    for (int tile = 0; tile < NTILES; tile++) {
        const int k0 = bk * KCHUNK + tile * KT;

        // Stage W[k0..k0+KT)[0:24) -> sw[pair][k&3][k>>2]; 12 iters @256 thr
#pragma unroll
        for (int it = 0; it < (KT * 6) / NTHREADS; it++) {
            int idx = tid + NTHREADS * it;
            int kk = idx / 6, q = idx % 6;
            float4 v = *(const float4*)(w + (size_t)(k0 + kk) * N_OUT + q * 4);
            int base = (kk & 3) * (KT / 4) + (kk >> 2);
            ((float2*)sw)[(2 * q + 0) * KT + base] = make_float2(v.x, v.y);
            ((float2*)sw)[(2 * q + 1) * KT + base] = make_float2(v.z, v.w);
        }
        __syncthreads();

#pragma unroll
        for (int i = 0; i < BIGS; i++) {   // fully unrolled: ring idx static
            const int gi = tile * BIGS + i;        // global big-iter
            const int slot = i & (DEPTH - 1);      // == gi % DEPTH (BIGS%DEPTH==0)
            float4 c0 = ring[slot][0], c1 = ring[slot][1];
            float4 c2 = ring[slot][2], c3 = ring[slot][3];
            const int gnext = gi + DEPTH;
            if (gnext < TOTBIG) {
                int off = gnext * 16 + kth;
                ring[slot][0] = __ldcs(xb0 + off);
                ring[slot][1] = __ldcs(xb1 + off);
                ring[slot][2] = __ldcs(xb2 + off);
                ring[slot][3] = __ldcs(xb3 + off);
            }

            const int kf4 = i * 16 + kth;   // float4 index within tile
#pragma unroll
            for (int s = 0; s < 4; s++) {
                u64 wp[6];
#pragma unroll
                for (int p = 0; p < 6; p++)
                    wp[p] = sw[(p6 + p) * KT + s * (KT / 4) + kf4];
                float xs0 = f4get(c0, s), xs1 = f4get(c1, s);
                float xs2 = f4get(c2, s), xs3 = f4get(c3, s);
                u64 X0 = pack2(xs0), X1 = pack2(xs1);
                u64 X2 = pack2(xs2), X3 = pack2(xs3);
#pragma unroll
                for (int p = 0; p < 6; p++) {
                    acc[0][p] = fma2(X0, wp[p], acc[0][p]);
                    acc[1][p] = fma2(X1, wp[p], acc[1][p]);
                    acc[2][p] = fma2(X2, wp[p], acc[2][p]);
                    acc[3][p] = fma2(X3, wp[p], acc[3][p]);
                }
                ss0 = fmaf(xs0, xs0, ss0);
                ss1 = fmaf(xs1, xs1, ss1);
                ss2 = fmaf(xs2, xs2, ss2);
                ss3 = fmaf(xs3, xs3, ss3);
            }
        }
        __syncthreads();
    }

    // Cross-kth reduction via smem (overlays weight buffer).
    float2* red = (float2*)smem;                                  // [32][16][PPAD]
    float* ssred = (float*)(smem + (size_t)MB * 16 * PPAD * 8);   // [32][16]
    {
        float ssl[RT] = {ss0, ss1, ss2, ss3};
#pragma unroll
        for (int r = 0; r < RT; r++) {
            int rl = wid * RT + r;
#pragma unroll
            for (int p = 0; p < 6; p++)
                red[((size_t)rl * 16 + kth) * PPAD + p6 + p] = u2f(acc[r][p]);
            if (half == 0) ssred[rl * 16 + kth] = ssl[r];
        }
    }
    __syncthreads();

    // 32 rows x 12 pairs = 384 columns
#pragma unroll
    for (int j = 0; j < 2; j++) {
        int col = j * NTHREADS + tid;
        if (col < MB * NP) {
            int p = col >> 5, rl = col & 31;  // lanes consecutive in rl -> coalesced
            float sx = 0.f, sy = 0.f;
#pragma unroll
            for (int t = 0; t < 16; t++) {
                float2 a = red[((size_t)rl * 16 + t) * PPAD + p];
                sx += a.x;
                sy += a.y;
            }
            g_hpart[bk][p][row0 + rl] = make_float2(sx, sy);
        }
    }
    if (tid < MB) {
        float s = 0.f;
#pragma unroll
        for (int t = 0; t < 16; t++) s += ssred[tid * 16 + t];
        g_sspart[bk][row0 + tid] = s;
    }
}

// ---------------------------------------------------------------------------
// Kernel B (known-good R4 form): 1 row/thread, grid 128 x 32.
// rcp.approx only; convergence checked every 8 iterations via
// multiply-compare. Cap 400 = reference MAX_IT^2.
// ---------------------------------------------------------------------------
extern "C" __global__ void __launch_bounds__(32)
mhc_finish_kernel(const float* __restrict__ bias, const float* __restrict__ alpha,
                  float* __restrict__ out) {
    int row = blockIdx.x * 32 + threadIdx.x;

    float h[N_OUT];
#pragma unroll
    for (int p = 0; p < NP; p++) {
        float sx = 0.f, sy = 0.f;
#pragma unroll
        for (int c = 0; c < KSPLIT; c++) {
            float2 a = g_hpart[c][p][row];
            sx += a.x;
            sy += a.y;
        }
        h[2 * p] = sx;
        h[2 * p + 1] = sy;
    }
    float ss = 0.f;
#pragma unroll
    for (int c = 0; c < KSPLIT; c++) ss += g_sspart[c][row];

    float r_inv = rsqrtf(ss * (1.0f / K_DIM));
    float a0 = alpha[0], a1 = alpha[1], a2 = alpha[2];

    float pre[HCN], post[HCN], H[HCN][HCN];
#pragma unroll
    for (int n = 0; n < HCN; n++) {
        float z0 = fmaf(r_inv * a0, h[n], bias[n]);
        pre[n] = 1.f / (1.f + __expf(-z0));
        float z1 = fmaf(r_inv * a1, h[HCN + n], bias[HCN + n]);
        post[n] = 2.f / (1.f + __expf(-z1));
    }
#pragma unroll
    for (int i = 0; i < HCN; i++)
#pragma unroll
        for (int j = 0; j < HCN; j++) {
            float z = fmaf(r_inv * a2, h[8 + 4 * i + j], bias[8 + 4 * i + j]);
            H[i][j] = __expf(z);
        }

    const float EPSV = 1e-12f;
    float u[4] = {1.f, 1.f, 1.f, 1.f}, v[4] = {1.f, 1.f, 1.f, 1.f};
    for (int o = 0; o < 50; o++) {          // 50 blocks x 8 iters = 400 max
        float vp0 = v[0], vp1 = v[1], vp2 = v[2], vp3 = v[3];
#pragma unroll
        for (int s = 0; s < 8; s++) {
            float nu[4];
#pragma unroll
            for (int i = 0; i < 4; i++) {
                float uv = fmaf(H[i][3], v[3],
                           fmaf(H[i][2], v[2],
                           fmaf(H[i][1], v[1],
                           fmaf(H[i][0], v[0], EPSV))));
                nu[i] = frcp(uv);
            }
#pragma unroll
            for (int j = 0; j < 4; j++) {
                float vu = fmaf(H[3][j], nu[3],
                           fmaf(H[2][j], nu[2],
                           fmaf(H[1][j], nu[1],
                           fmaf(H[0][j], nu[0], EPSV))));
                v[j] = frcp(vu);
            }
            u[0] = nu[0]; u[1] = nu[1]; u[2] = nu[2]; u[3] = nu[3];
        }
        float m = fabsf(v[0] - vp0) - 1e-6f * fabsf(v[0]);
        m = fmaxf(m, fabsf(v[1] - vp1) - 1e-6f * fabsf(v[1]));
        m = fmaxf(m, fabsf(v[2] - vp2) - 1e-6f * fabsf(v[2]));
        m = fmaxf(m, fabsf(v[3] - vp3) - 1e-6f * fabsf(v[3]));
        if (m <= 0.f) break;
    }

    ((float4*)out)[row] = make_float4(pre[0], pre[1], pre[2], pre[3]);
    ((float4*)(out + (size_t)T_DIM * HCN))[row] =
        make_float4(post[0], post[1], post[2], post[3]);
    float4* res = (float4*)(out + 2 * (size_t)T_DIM * HCN + (size_t)row * 16);
#pragma unroll
    for (int i = 0; i < 4; i++) {
        res[i] = make_float4(u[i] * H[i][0] * v[0], u[i] * H[i][1] * v[1],
                             u[i] * H[i][2] * v[2], u[i] * H[i][3] * v[3]);
    }
}

// No-op kernel: shifts ncu's "-s 5 -c 1" capture window (launch #6) onto the
// GEMM kernel (pattern per call = [gemm, finish, d, d, d] -> #6 = gemm).
extern "C" __global__ void mhc_dummy_kernel() {}

// ---------------------------------------------------------------------------
// smem: max(staging 12*KT*8 = 49152, reduction 32*16*13*8 + 32*16*4 = 55296)
#define SMEM_BYTES 55296

extern "C" void kernel_launch(void* const* d_in, const int* in_sizes, int n_in,
                              void* d_out, int out_size) {
    const float* x = (const float*)d_in[0];
    const float* w = (const float*)d_in[1];
    const float* bias = (const float*)d_in[2];
    const float* alpha = (const float*)d_in[3];
    float* out = (float*)d_out;

    cudaFuncSetAttribute(mhc_gemm_kernel,
                         cudaFuncAttributeMaxDynamicSharedMemorySize,
                         SMEM_BYTES);

    dim3 grid(T_DIM / MB, KSPLIT);
    mhc_gemm_kernel<<<grid, NTHREADS, SMEM_BYTES>>>(x, w);
    mhc_finish_kernel<<<T_DIM / 32, 32>>>(bias, alpha, out);
    mhc_dummy_kernel<<<1, 32>>>();
    mhc_dummy_kernel<<<1, 32>>>();
    mhc_dummy_kernel<<<1, 32>>>();
}

// round 7
// speedup vs baseline: 1.2869x; 1.0007x over previous
#include <cuda_runtime.h>

#define T_DIM 4096
#define K_DIM 16384
#define HCN 4
#define N_OUT 24
#define NP 12          // float2 pairs across N
#define MB 64          // rows per CTA
#define KSPLIT 8
#define KCHUNK (K_DIM / KSPLIT)   // 2048
#define KT 512         // K tile staged in smem
#define NTILES (KCHUNK / KT)      // 4
#define BIGS (KT / 64)            // 8 big-iters (64 k) per tile
#define TOTBIG (NTILES * BIGS)    // 32 big-iters per chunk
#define RT 8           // rows per warp (bytes/FMA halved vs RT=4)
#define DEPTH 2        // x prefetch ring depth
#define NTHREADS 256
#define PPAD 13        // padded pair stride for reduction

// Scratch (device globals). Transposed [split][pair][row] for coalesced reads.
__device__ float2 g_hpart[KSPLIT][NP][T_DIM];
__device__ float  g_sspart[KSPLIT][T_DIM];

using u64 = unsigned long long;

__device__ __forceinline__ u64 fma2(u64 a, u64 b, u64 c) {
    u64 d;
    asm("fma.rn.f32x2 %0, %1, %2, %3;" : "=l"(d) : "l"(a), "l"(b), "l"(c));
    return d;
}
__device__ __forceinline__ u64 pack2(float x) {
    u64 d;
    asm("mov.b64 %0, {%1, %1};" : "=l"(d) : "f"(x));
    return d;
}
__device__ __forceinline__ float2 u2f(u64 a) {
    float2 f;
    asm("mov.b64 {%0, %1}, %2;" : "=f"(f.x), "=f"(f.y) : "l"(a));
    return f;
}
__device__ __forceinline__ float frcp(float a) {
    float r;
    asm("rcp.approx.f32 %0, %1;" : "=f"(r) : "f"(a));
    return r;
}
__device__ __forceinline__ float f4get(const float4& v, int s) {
    return s == 0 ? v.x : (s == 1 ? v.y : (s == 2 ? v.z : v.w));
}

// ---------------------------------------------------------------------------
// Kernel A. Warp layout: lane = half*16 + kth. Each warp owns RT=8 rows;
// lanes 0-15 accumulate pairs 0-5, lanes 16-31 pairs 6-11 (same rows/k; the
// duplicate x addresses across halves dedup within the warp instruction).
// RT=8 halves weight-LDS bytes per FMA (crossbar ~43% vs co-bound at RT=4).
// 256 threads, ~208 regs (no cap, no spills), depth-2 x ring.
// ---------------------------------------------------------------------------
extern "C" __global__ void __launch_bounds__(NTHREADS, 1)
mhc_gemm_kernel(const float* __restrict__ x, const float* __restrict__ w) {
    extern __shared__ char smem[];
    u64* sw = (u64*)smem;  // [NP][4 phases][KT/4] u64 (float2 pairs)

    const int tid = threadIdx.x;
    const int wid = tid >> 5;          // warp 0..7
    const int half = (tid >> 4) & 1;   // N-half
    const int kth = tid & 15;          // k lane
    const int p6 = half * 6;
    const int bm = blockIdx.x;
    const int bk = blockIdx.y;
    const int row0 = bm * MB;
    const int rbase = row0 + wid * RT;

    // base float4 pointer for row rbase within this k-chunk; rows are
    // K_DIM/4 = 4096 float4 apart.
    const float4* xb = (const float4*)(x + (size_t)rbase * K_DIM) + bk * (KCHUNK / 4);

    u64 acc[RT][6];
    float ss[RT];
#pragma unroll
    for (int r = 0; r < RT; r++) {
        ss[r] = 0.f;
#pragma unroll
        for (int p = 0; p < 6; p++) acc[r][p] = 0ull;
    }

    // Preload prefetch ring: big-iters 0..DEPTH-1
    float4 ring[DEPTH][RT];
#pragma unroll
    for (int st = 0; st < DEPTH; st++) {
        int off = st * 16 + kth;
#pragma unroll
        for (int r = 0; r < RT; r++)
            ring[st][r] = __ldcs(xb + (size_t)r * (K_DIM / 4) + off);
    }

    for (int tile = 0; tile < NTILES; tile++) {
        const int k0 = bk * KCHUNK + tile * KT;

        // Stage W[k0..k0+KT)[0:24) -> sw[pair][k&3][k>>2]; 12 iters @256 thr
#pragma unroll
        for (int it = 0; it < (KT * 6) / NTHREADS; it++) {
            int idx = tid + NTHREADS * it;
            int kk = idx / 6, q = idx % 6;
            float4 v = *(const float4*)(w + (size_t)(k0 + kk) * N_OUT + q * 4);
            int base = (kk & 3) * (KT / 4) + (kk >> 2);
            ((float2*)sw)[(2 * q + 0) * KT + base] = make_float2(v.x, v.y);
            ((float2*)sw)[(2 * q + 1) * KT + base] = make_float2(v.z, v.w);
        }
        __syncthreads();

#pragma unroll
        for (int i = 0; i < BIGS; i++) {   // unrolled: ring slot index static
            const int gi = tile * BIGS + i;
            const int slot = i & (DEPTH - 1);   // == gi % DEPTH
            float4 cur[RT];
#pragma unroll
            for (int r = 0; r < RT; r++) cur[r] = ring[slot][r];
            const int gnext = gi + DEPTH;
            if (gnext < TOTBIG) {
                int off = gnext * 16 + kth;
#pragma unroll
                for (int r = 0; r < RT; r++)
                    ring[slot][r] = __ldcs(xb + (size_t)r * (K_DIM / 4) + off);
            }

            const int kf4 = i * 16 + kth;   // float4 index within tile [0,128)
#pragma unroll
            for (int s = 0; s < 4; s++) {
                u64 wp[6];
#pragma unroll
                for (int p = 0; p < 6; p++)
                    wp[p] = sw[(p6 + p) * KT + s * (KT / 4) + kf4];
#pragma unroll
                for (int r = 0; r < RT; r++) {
                    float xs = f4get(cur[r], s);
                    u64 X = pack2(xs);
#pragma unroll
                    for (int p = 0; p < 6; p++)
                        acc[r][p] = fma2(X, wp[p], acc[r][p]);
                    ss[r] = fmaf(xs, xs, ss[r]);
                }
            }
        }
        __syncthreads();
    }

    // Cross-kth reduction via smem (overlays weight buffer).
    float2* red = (float2*)smem;                                  // [64][16][PPAD]
    float* ssred = (float*)(smem + (size_t)MB * 16 * PPAD * 8);   // [64][16]
#pragma unroll
    for (int r = 0; r < RT; r++) {
        int rl = wid * RT + r;
#pragma unroll
        for (int p = 0; p < 6; p++)
            red[((size_t)rl * 16 + kth) * PPAD + p6 + p] = u2f(acc[r][p]);
        if (half == 0) ssred[rl * 16 + kth] = ss[r];
    }
    __syncthreads();

    // 64 rows x 12 pairs = 768 columns; 3 per thread
#pragma unroll
    for (int j = 0; j < 3; j++) {
        int col = j * NTHREADS + tid;
        int p = col >> 6, rl = col & 63;  // lanes consecutive in rl -> coalesced
        float sx = 0.f, sy = 0.f;
#pragma unroll
        for (int t = 0; t < 16; t++) {
            float2 a = red[((size_t)rl * 16 + t) * PPAD + p];
            sx += a.x;
            sy += a.y;
        }
        g_hpart[bk][p][row0 + rl] = make_float2(sx, sy);
    }
    if (tid < MB) {
        float s = 0.f;
#pragma unroll
        for (int t = 0; t < 16; t++) s += ssred[tid * 16 + t];
        g_sspart[bk][row0 + tid] = s;
    }
}

// ---------------------------------------------------------------------------
// Kernel B (known-good R4 form): 1 row/thread, grid 128 x 32.
// rcp.approx only; convergence checked every 8 iterations via
// multiply-compare. Cap 400 = reference MAX_IT^2.
// ---------------------------------------------------------------------------
extern "C" __global__ void __launch_bounds__(32)
mhc_finish_kernel(const float* __restrict__ bias, const float* __restrict__ alpha,
                  float* __restrict__ out) {
    int row = blockIdx.x * 32 + threadIdx.x;

    float h[N_OUT];
#pragma unroll
    for (int p = 0; p < NP; p++) {
        float sx = 0.f, sy = 0.f;
#pragma unroll
        for (int c = 0; c < KSPLIT; c++) {
            float2 a = g_hpart[c][p][row];
            sx += a.x;
            sy += a.y;
        }
        h[2 * p] = sx;
        h[2 * p + 1] = sy;
    }
    float ss = 0.f;
#pragma unroll
    for (int c = 0; c < KSPLIT; c++) ss += g_sspart[c][row];

    float r_inv = rsqrtf(ss * (1.0f / K_DIM));
    float a0 = alpha[0], a1 = alpha[1], a2 = alpha[2];

    float pre[HCN], post[HCN], H[HCN][HCN];
#pragma unroll
    for (int n = 0; n < HCN; n++) {
        float z0 = fmaf(r_inv * a0, h[n], bias[n]);
        pre[n] = 1.f / (1.f + __expf(-z0));
        float z1 = fmaf(r_inv * a1, h[HCN + n], bias[HCN + n]);
        post[n] = 2.f / (1.f + __expf(-z1));
    }
#pragma unroll
    for (int i = 0; i < HCN; i++)
#pragma unroll
        for (int j = 0; j < HCN; j++) {
            float z = fmaf(r_inv * a2, h[8 + 4 * i + j], bias[8 + 4 * i + j]);
            H[i][j] = __expf(z);
        }

    const float EPSV = 1e-12f;
    float u[4] = {1.f, 1.f, 1.f, 1.f}, v[4] = {1.f, 1.f, 1.f, 1.f};
    for (int o = 0; o < 50; o++) {          // 50 blocks x 8 iters = 400 max
        float vp0 = v[0], vp1 = v[1], vp2 = v[2], vp3 = v[3];
#pragma unroll
        for (int s = 0; s < 8; s++) {
            float nu[4];
#pragma unroll
            for (int i = 0; i < 4; i++) {
                float uv = fmaf(H[i][3], v[3],
                           fmaf(H[i][2], v[2],
                           fmaf(H[i][1], v[1],
                           fmaf(H[i][0], v[0], EPSV))));
                nu[i] = frcp(uv);
            }
#pragma unroll
            for (int j = 0; j < 4; j++) {
                float vu = fmaf(H[3][j], nu[3],
                           fmaf(H[2][j], nu[2],
                           fmaf(H[1][j], nu[1],
                           fmaf(H[0][j], nu[0], EPSV))));
                v[j] = frcp(vu);
            }
            u[0] = nu[0]; u[1] = nu[1]; u[2] = nu[2]; u[3] = nu[3];
        }
        float m = fabsf(v[0] - vp0) - 1e-6f * fabsf(v[0]);
        m = fmaxf(m, fabsf(v[1] - vp1) - 1e-6f * fabsf(v[1]));
        m = fmaxf(m, fabsf(v[2] - vp2) - 1e-6f * fabsf(v[2]));
        m = fmaxf(m, fabsf(v[3] - vp3) - 1e-6f * fabsf(v[3]));
        if (m <= 0.f) break;
    }

    ((float4*)out)[row] = make_float4(pre[0], pre[1], pre[2], pre[3]);
    ((float4*)(out + (size_t)T_DIM * HCN))[row] =
        make_float4(post[0], post[1], post[2], post[3]);
    float4* res = (float4*)(out + 2 * (size_t)T_DIM * HCN + (size_t)row * 16);
#pragma unroll
    for (int i = 0; i < 4; i++) {
        res[i] = make_float4(u[i] * H[i][0] * v[0], u[i] * H[i][1] * v[1],
                             u[i] * H[i][2] * v[2], u[i] * H[i][3] * v[3]);
    }
}

// ---------------------------------------------------------------------------
// smem: max(staging 12*KT*8 = 49152, reduction 64*16*13*8 + 64*16*4 = 110592)
#define SMEM_BYTES 110592

extern "C" void kernel_launch(void* const* d_in, const int* in_sizes, int n_in,
                              void* d_out, int out_size) {
    const float* x = (const float*)d_in[0];
    const float* w = (const float*)d_in[1];
    const float* bias = (const float*)d_in[2];
    const float* alpha = (const float*)d_in[3];
    float* out = (float*)d_out;

    cudaFuncSetAttribute(mhc_gemm_kernel,
                         cudaFuncAttributeMaxDynamicSharedMemorySize,
                         SMEM_BYTES);

    dim3 grid(T_DIM / MB, KSPLIT);
    // PROFILING ROUND: linear chain g -> f -> g so ncu's "-s 5 -c 1" (6th
    // launch) lands on the GEMM: 1g 2f 3g | 4g 5f [6g]. The trailing GEMM
    // is idempotent (rewrites identical partials already consumed by finish)
    // so output is unchanged; it will be removed next round.
    mhc_gemm_kernel<<<grid, NTHREADS, SMEM_BYTES>>>(x, w);
    mhc_finish_kernel<<<T_DIM / 32, 32>>>(bias, alpha, out);
    mhc_gemm_kernel<<<grid, NTHREADS, SMEM_BYTES>>>(x, w);
}

// round 8
// speedup vs baseline: 2.1238x; 1.6503x over previous
#include <cuda_runtime.h>

#define T_DIM 4096
#define K_DIM 16384
#define HCN 4
#define N_OUT 24
#define NP 12          // float2 pairs across N
#define MB 64          // rows per CTA (8 warps x RT)
#define KSPLIT 8
#define KCHUNK (K_DIM / KSPLIT)   // 2048
#define KT 512         // K tile staged in smem
#define NTILES (KCHUNK / KT)      // 4
#define BIGS (KT / 32)            // 16 big-iters (32 k) per tile
#define TOTBIG (NTILES * BIGS)    // 64 big-iters per chunk
#define RT 8           // rows per warp
#define DEPTH 2        // x prefetch ring depth
#define NTHREADS 256
#define PSTRIDE 524    // u64 stride per pair in smem (524%16=12 -> conflict-free)
#define PPAD 13        // padded pair stride for reduction

// Scratch (device globals). Transposed [split][pair][row] for coalesced reads.
__device__ float2 g_hpart[KSPLIT][NP][T_DIM];
__device__ float  g_sspart[KSPLIT][T_DIM];

using u64 = unsigned long long;

__device__ __forceinline__ u64 fma2(u64 a, u64 b, u64 c) {
    u64 d;
    asm("fma.rn.f32x2 %0, %1, %2, %3;" : "=l"(d) : "l"(a), "l"(b), "l"(c));
    return d;
}
__device__ __forceinline__ u64 pack2(float x) {
    u64 d;
    asm("mov.b64 %0, {%1, %1};" : "=l"(d) : "f"(x));
    return d;
}
__device__ __forceinline__ float2 u2f(u64 a) {
    float2 f;
    asm("mov.b64 {%0, %1}, %2;" : "=f"(f.x), "=f"(f.y) : "l"(a));
    return f;
}
__device__ __forceinline__ float frcp(float a) {
    float r;
    asm("rcp.approx.f32 %0, %1;" : "=f"(r) : "f"(a));
    return r;
}
__device__ __forceinline__ float f4get(const float4& v, int s) {
    return s == 0 ? v.x : (s == 1 ? v.y : (s == 2 ? v.z : v.w));
}

// ---------------------------------------------------------------------------
// Kernel A — quarter-split: lane = g*8 + l7; group g in [0,4) owns output
// pairs [3g, 3g+3); l7 is the k-lane (8 distinct float4 per big-iter = 32 k).
// Each warp owns RT=8 rows. acc[8][3] u64 = 48 regs -> NO spills (~155 total).
// Crossbar:fma2 ratio 3:24 = RT=8 balance. Pair stride 524 u64 makes the
// 4-group LDS.64 conflict-free (each bank hit exactly twice).
// x: depth-2 ring, consume-then-prefetch (no cur copy), ~1 big-iter of cover.
// ---------------------------------------------------------------------------
extern "C" __global__ void __launch_bounds__(NTHREADS, 1)
mhc_gemm_kernel(const float* __restrict__ x, const float* __restrict__ w) {
    extern __shared__ char smem[];
    u64* sw = (u64*)smem;  // [12 pairs][PSTRIDE u64]; inner: [4 phases][128 kf4]

    const int tid = threadIdx.x;
    const int wid = tid >> 5;          // warp 0..7
    const int g   = (tid >> 3) & 3;    // pair group 0..3
    const int l7  = tid & 7;           // k lane 0..7
    const int p3  = g * 3;             // first pair owned by this group
    const int bm = blockIdx.x;
    const int bk = blockIdx.y;
    const int row0 = bm * MB;
    const int rbase = row0 + wid * RT;

    // base float4 pointer for row rbase within this k-chunk
    const float4* xb = (const float4*)(x + (size_t)rbase * K_DIM) + bk * (KCHUNK / 4);

    u64 acc[RT][3];
    float ss[RT];
#pragma unroll
    for (int r = 0; r < RT; r++) {
        ss[r] = 0.f;
#pragma unroll
        for (int j = 0; j < 3; j++) acc[r][j] = 0ull;
    }

    // Preload ring: big-iters 0..DEPTH-1 (8 float4 per big-iter per row set;
    // lane loads its l7-th float4 of each row; 4 groups duplicate -> 1 line)
    float4 ring[DEPTH][RT];
#pragma unroll
    for (int st = 0; st < DEPTH; st++) {
        int off = st * 8 + l7;
#pragma unroll
        for (int r = 0; r < RT; r++)
            ring[st][r] = __ldcs(xb + (size_t)r * (K_DIM / 4) + off);
    }

    for (int tile = 0; tile < NTILES; tile++) {
        const int k0 = bk * KCHUNK + tile * KT;

        // Stage W[k0..k0+KT)[0:24) -> sw[p][ (k&3)*128 + (k>>2) ]
#pragma unroll
        for (int it = 0; it < (KT * 6) / NTHREADS; it++) {
            int idx = tid + NTHREADS * it;
            int kk = idx / 6, q = idx % 6;
            float4 v = *(const float4*)(w + (size_t)(k0 + kk) * N_OUT + q * 4);
            int base = (kk & 3) * 128 + (kk >> 2);
            ((float2*)sw)[(2 * q + 0) * PSTRIDE + base] = make_float2(v.x, v.y);
            ((float2*)sw)[(2 * q + 1) * PSTRIDE + base] = make_float2(v.z, v.w);
        }
        __syncthreads();

#pragma unroll 2
        for (int i = 0; i < BIGS; i++) {
            const int gi = tile * BIGS + i;
            const int slot = i & (DEPTH - 1);
            const int kf4 = i * 8 + l7;   // float4 index within tile [0,128)

#pragma unroll
            for (int s = 0; s < 4; s++) {
                u64 wp[3];
#pragma unroll
                for (int j = 0; j < 3; j++)
                    wp[j] = sw[(p3 + j) * PSTRIDE + s * 128 + kf4];
#pragma unroll
                for (int r = 0; r < RT; r++) {
                    float xs = f4get(ring[slot][r], s);
                    u64 X = pack2(xs);
#pragma unroll
                    for (int j = 0; j < 3; j++)
                        acc[r][j] = fma2(X, wp[j], acc[r][j]);
                    ss[r] = fmaf(xs, xs, ss[r]);
                }
            }

            // consume-then-prefetch: reload this slot for big-iter gi+DEPTH
            int gnext = gi + DEPTH;
            if (gnext > TOTBIG - 1) gnext = TOTBIG - 1;  // tail: redundant reload
            {
                int off = gnext * 8 + l7;
#pragma unroll
                for (int r = 0; r < RT; r++)
                    ring[slot][r] = __ldcs(xb + (size_t)r * (K_DIM / 4) + off);
            }
        }
        __syncthreads();
    }

    // Cross-k-lane reduction via smem (overlays weight buffer).
    float2* red = (float2*)smem;                                 // [64][8][PPAD]
    float* ssred = (float*)(smem + (size_t)MB * 8 * PPAD * 8);   // [64][8]
#pragma unroll
    for (int r = 0; r < RT; r++) {
        int rl = wid * RT + r;
#pragma unroll
        for (int j = 0; j < 3; j++)
            red[((size_t)rl * 8 + l7) * PPAD + p3 + j] = u2f(acc[r][j]);
        if (g == 0) ssred[rl * 8 + l7] = ss[r];   // groups duplicate ss
    }
    __syncthreads();

    // 64 rows x 12 pairs = 768 columns; 3 per thread
#pragma unroll
    for (int jj = 0; jj < 3; jj++) {
        int col = jj * NTHREADS + tid;
        int p = col >> 6, rl = col & 63;  // lanes consecutive in rl -> coalesced
        float sx = 0.f, sy = 0.f;
#pragma unroll
        for (int t = 0; t < 8; t++) {
            float2 a = red[((size_t)rl * 8 + t) * PPAD + p];
            sx += a.x;
            sy += a.y;
        }
        g_hpart[bk][p][row0 + rl] = make_float2(sx, sy);
    }
    if (tid < MB) {
        float s = 0.f;
#pragma unroll
        for (int t = 0; t < 8; t++) s += ssred[tid * 8 + t];
        g_sspart[bk][row0 + tid] = s;
    }
}

// ---------------------------------------------------------------------------
// Kernel B (known-good R4 form): 1 row/thread, grid 128 x 32.
// rcp.approx only; convergence checked every 8 iterations via
// multiply-compare. Cap 400 = reference MAX_IT^2.
// ---------------------------------------------------------------------------
extern "C" __global__ void __launch_bounds__(32)
mhc_finish_kernel(const float* __restrict__ bias, const float* __restrict__ alpha,
                  float* __restrict__ out) {
    int row = blockIdx.x * 32 + threadIdx.x;

    float h[N_OUT];
#pragma unroll
    for (int p = 0; p < NP; p++) {
        float sx = 0.f, sy = 0.f;
#pragma unroll
        for (int c = 0; c < KSPLIT; c++) {
            float2 a = g_hpart[c][p][row];
            sx += a.x;
            sy += a.y;
        }
        h[2 * p] = sx;
        h[2 * p + 1] = sy;
    }
    float ss = 0.f;
#pragma unroll
    for (int c = 0; c < KSPLIT; c++) ss += g_sspart[c][row];

    float r_inv = rsqrtf(ss * (1.0f / K_DIM));
    float a0 = alpha[0], a1 = alpha[1], a2 = alpha[2];

    float pre[HCN], post[HCN], H[HCN][HCN];
#pragma unroll
    for (int n = 0; n < HCN; n++) {
        float z0 = fmaf(r_inv * a0, h[n], bias[n]);
        pre[n] = 1.f / (1.f + __expf(-z0));
        float z1 = fmaf(r_inv * a1, h[HCN + n], bias[HCN + n]);
        post[n] = 2.f / (1.f + __expf(-z1));
    }
#pragma unroll
    for (int i = 0; i < HCN; i++)
#pragma unroll
        for (int j = 0; j < HCN; j++) {
            float z = fmaf(r_inv * a2, h[8 + 4 * i + j], bias[8 + 4 * i + j]);
            H[i][j] = __expf(z);
        }

    const float EPSV = 1e-12f;
    float u[4] = {1.f, 1.f, 1.f, 1.f}, v[4] = {1.f, 1.f, 1.f, 1.f};
    for (int o = 0; o < 50; o++) {          // 50 blocks x 8 iters = 400 max
        float vp0 = v[0], vp1 = v[1], vp2 = v[2], vp3 = v[3];
#pragma unroll
        for (int s = 0; s < 8; s++) {
            float nu[4];
#pragma unroll
            for (int i = 0; i < 4; i++) {
                float uv = fmaf(H[i][3], v[3],
                           fmaf(H[i][2], v[2],
                           fmaf(H[i][1], v[1],
                           fmaf(H[i][0], v[0], EPSV))));
                nu[i] = frcp(uv);
            }
#pragma unroll
            for (int j = 0; j < 4; j++) {
                float vu = fmaf(H[3][j], nu[3],
                           fmaf(H[2][j], nu[2],
                           fmaf(H[1][j], nu[1],
                           fmaf(H[0][j], nu[0], EPSV))));
                v[j] = frcp(vu);
            }
            u[0] = nu[0]; u[1] = nu[1]; u[2] = nu[2]; u[3] = nu[3];
        }
        float m = fabsf(v[0] - vp0) - 1e-6f * fabsf(v[0]);
        m = fmaxf(m, fabsf(v[1] - vp1) - 1e-6f * fabsf(v[1]));
        m = fmaxf(m, fabsf(v[2] - vp2) - 1e-6f * fabsf(v[2]));
        m = fmaxf(m, fabsf(v[3] - vp3) - 1e-6f * fabsf(v[3]));
        if (m <= 0.f) break;
    }

    ((float4*)out)[row] = make_float4(pre[0], pre[1], pre[2], pre[3]);
    ((float4*)(out + (size_t)T_DIM * HCN))[row] =
        make_float4(post[0], post[1], post[2], post[3]);
    float4* res = (float4*)(out + 2 * (size_t)T_DIM * HCN + (size_t)row * 16);
#pragma unroll
    for (int i = 0; i < 4; i++) {
        res[i] = make_float4(u[i] * H[i][0] * v[0], u[i] * H[i][1] * v[1],
                             u[i] * H[i][2] * v[2], u[i] * H[i][3] * v[3]);
    }
}

// ---------------------------------------------------------------------------
// smem: max(staging 12*PSTRIDE*8 = 50304, reduction 64*8*13*8 + 64*8*4 = 55296)
#define SMEM_BYTES 55296

extern "C" void kernel_launch(void* const* d_in, const int* in_sizes, int n_in,
                              void* d_out, int out_size) {
    const float* x = (const float*)d_in[0];
    const float* w = (const float*)d_in[1];
    const float* bias = (const float*)d_in[2];
    const float* alpha = (const float*)d_in[3];
    float* out = (float*)d_out;

    cudaFuncSetAttribute(mhc_gemm_kernel,
                         cudaFuncAttributeMaxDynamicSharedMemorySize,
                         SMEM_BYTES);

    dim3 grid(T_DIM / MB, KSPLIT);
    mhc_gemm_kernel<<<grid, NTHREADS, SMEM_BYTES>>>(x, w);
    mhc_finish_kernel<<<T_DIM / 32, 32>>>(bias, alpha, out);
}

// round 9
// speedup vs baseline: 2.3796x; 1.1204x over previous
#include <cuda_runtime.h>
#include <cstdint>

#define T_DIM 4096
#define K_DIM 16384
#define HCN 4
#define N_OUT 24
#define NP 12          // float2 pairs across N
#define MB 64          // rows per CTA (8 warps x RT)
#define KSPLIT 8
#define KCHUNK (K_DIM / KSPLIT)   // 2048
#define KT 512         // weight K tile staged in smem
#define NTILES (KCHUNK / KT)      // 4
#define RT 8           // rows per warp
#define NTHREADS 256
#define PSTRIDE 524    // u64 stride per pair in smem (524%16=12 -> conflict-free)
#define PPAD 13        // padded pair stride for reduction

#define STAGE_K 64                 // k per x pipeline stage
#define NSTG (KCHUNK / STAGE_K)    // 32 stages per chunk
#define NSLOTS 4                   // x smem slots (reuse distance 3)
#define XSLOT_BYTES (MB * STAGE_K * 4)        // 16384
#define WBYTES (NP * PSTRIDE * 8)             // 50304
#define SMEM_BYTES (WBYTES + NSLOTS * XSLOT_BYTES)  // 115840

// Scratch (device globals). Transposed [split][pair][row] for coalesced reads.
__device__ float2 g_hpart[KSPLIT][NP][T_DIM];
__device__ float  g_sspart[KSPLIT][T_DIM];

using u64 = unsigned long long;

__device__ __forceinline__ u64 fma2(u64 a, u64 b, u64 c) {
    u64 d;
    asm("fma.rn.f32x2 %0, %1, %2, %3;" : "=l"(d) : "l"(a), "l"(b), "l"(c));
    return d;
}
__device__ __forceinline__ u64 pack2(float x) {
    u64 d;
    asm("mov.b64 %0, {%1, %1};" : "=l"(d) : "f"(x));
    return d;
}
__device__ __forceinline__ float2 u2f(u64 a) {
    float2 f;
    asm("mov.b64 {%0, %1}, %2;" : "=f"(f.x), "=f"(f.y) : "l"(a));
    return f;
}
__device__ __forceinline__ float frcp(float a) {
    float r;
    asm("rcp.approx.f32 %0, %1;" : "=f"(r) : "f"(a));
    return r;
}
__device__ __forceinline__ float f4get(const float4& v, int s) {
    return s == 0 ? v.x : (s == 1 ? v.y : (s == 2 ? v.z : v.w));
}
__device__ __forceinline__ void cp_async16(uint32_t dst_smem, const void* src) {
    asm volatile("cp.async.cg.shared.global [%0], [%1], 16;"
                 :: "r"(dst_smem), "l"(src));
}
__device__ __forceinline__ void cp_commit() {
    asm volatile("cp.async.commit_group;");
}
template <int N>
__device__ __forceinline__ void cp_wait() {
    asm volatile("cp.async.wait_group %0;" :: "n"(N));
}

// ---------------------------------------------------------------------------
// Kernel A — quarter-split compute (R8 core) + cp.async x pipeline.
// Warp: lane = g*8 + l7; group g owns output pairs [3g,3g+3); l7 = k lane.
// Each warp owns RT=8 rows; acc[8][3] u64 = 48 regs, ~120 total (no spills).
// x flows GMEM -> smem via 4-slot cp.async.cg pipeline (32KB in flight/SM),
// removing the register-MLP cap that pinned x streaming at ~1.6 TB/s.
// ---------------------------------------------------------------------------
extern "C" __global__ void __launch_bounds__(NTHREADS, 1)
mhc_gemm_kernel(const float* __restrict__ x, const float* __restrict__ w) {
    extern __shared__ char smem[];
    u64* sw = (u64*)smem;  // weights: [12 pairs][PSTRIDE u64]
    const uint32_t smem_u32 = (uint32_t)__cvta_generic_to_shared(smem);
    const uint32_t xbase = smem_u32 + WBYTES;

    const int tid = threadIdx.x;
    const int wid = tid >> 5;          // warp 0..7
    const int g   = (tid >> 3) & 3;    // pair group 0..3
    const int l7  = tid & 7;           // k lane 0..7
    const int p3  = g * 3;
    const int bm = blockIdx.x;
    const int bk = blockIdx.y;
    const int row0 = bm * MB;

    // x fill mapping: thread t copies 4x16B for row = t>>2, quarter q = t&3
    const int frow = tid >> 2, fq = tid & 3;
    const float* fsrc_base =
        x + (size_t)(row0 + frow) * K_DIM + bk * KCHUNK + fq * 16;
    const uint32_t fdst_base = xbase + (uint32_t)(frow * (STAGE_K * 4) + fq * 64);

    u64 acc[RT][3];
    float ss[RT];
#pragma unroll
    for (int r = 0; r < RT; r++) {
        ss[r] = 0.f;
#pragma unroll
        for (int j = 0; j < 3; j++) acc[r][j] = 0ull;
    }

    // Prologue: fill stages 0,1,2
#pragma unroll
    for (int st = 0; st < NSLOTS - 1; st++) {
        const float* src = fsrc_base + st * STAGE_K;
        uint32_t dst = fdst_base + (st & (NSLOTS - 1)) * XSLOT_BYTES;
#pragma unroll
        for (int i = 0; i < 4; i++)
            cp_async16(dst + i * 16, src + i * 4);
        cp_commit();
    }

    for (int tile = 0; tile < NTILES; tile++) {
        const int k0 = bk * KCHUNK + tile * KT;

        __syncthreads();   // prev tile's compute done before restaging weights
        // Stage W[k0..k0+KT)[0:24) -> sw[p][(k&3)*128 + (k>>2)]
#pragma unroll
        for (int it = 0; it < (KT * 6) / NTHREADS; it++) {
            int idx = tid + NTHREADS * it;
            int kk = idx / 6, q = idx % 6;
            float4 v = *(const float4*)(w + (size_t)(k0 + kk) * N_OUT + q * 4);
            int base = (kk & 3) * 128 + (kk >> 2);
            ((float2*)sw)[(2 * q + 0) * PSTRIDE + base] = make_float2(v.x, v.y);
            ((float2*)sw)[(2 * q + 1) * PSTRIDE + base] = make_float2(v.z, v.w);
        }

        for (int j = 0; j < KT / STAGE_K; j++) {   // 8 x-stages per weight tile
            const int st = tile * (KT / STAGE_K) + j;
            const int slot = st & (NSLOTS - 1);

            cp_wait<2>();        // stage st landed (st+1, st+2 may be in flight)
            __syncthreads();     // visible to all; also: slot st-? safe to refill

            // Compute 2 big-iters (32 k each) from x slot + weight tile.
            const char* xs = smem + WBYTES + slot * XSLOT_BYTES;
#pragma unroll
            for (int bi = 0; bi < 2; bi++) {
                float4 xv[RT];
#pragma unroll
                for (int r = 0; r < RT; r++)
                    xv[r] = *(const float4*)(xs +
                        (((wid * RT + r) * 16 + bi * 8 + l7) << 4));
                const int kf4 = j * 16 + bi * 8 + l7;  // within weight tile
#pragma unroll
                for (int s = 0; s < 4; s++) {
                    u64 wp[3];
#pragma unroll
                    for (int jj = 0; jj < 3; jj++)
                        wp[jj] = sw[(p3 + jj) * PSTRIDE + s * 128 + kf4];
#pragma unroll
                    for (int r = 0; r < RT; r++) {
                        float xsv = f4get(xv[r], s);
                        u64 X = pack2(xsv);
#pragma unroll
                        for (int jj = 0; jj < 3; jj++)
                            acc[r][jj] = fma2(X, wp[jj], acc[r][jj]);
                        ss[r] = fmaf(xsv, xsv, ss[r]);
                    }
                }
            }

            // Refill: stage st+3 into slot (st+3)&3 == (st-1)&3, whose data
            // was consumed at iter st-1 (all threads passed this iter's sync).
            if (st + NSLOTS - 1 < NSTG) {
                const float* src = fsrc_base + (st + NSLOTS - 1) * STAGE_K;
                uint32_t dst = fdst_base + ((st + NSLOTS - 1) & (NSLOTS - 1)) * XSLOT_BYTES;
#pragma unroll
                for (int i = 0; i < 4; i++)
                    cp_async16(dst + i * 16, src + i * 4);
            }
            cp_commit();   // keep group count in lockstep with stage index
        }
    }

    cp_wait<0>();
    __syncthreads();

    // Cross-k-lane reduction via smem (overlays weight buffer + x slot 0).
    float2* red = (float2*)smem;                                 // [64][8][PPAD]
    float* ssred = (float*)(smem + (size_t)MB * 8 * PPAD * 8);   // [64][8]
#pragma unroll
    for (int r = 0; r < RT; r++) {
        int rl = wid * RT + r;
#pragma unroll
        for (int j = 0; j < 3; j++)
            red[((size_t)rl * 8 + l7) * PPAD + p3 + j] = u2f(acc[r][j]);
        if (g == 0) ssred[rl * 8 + l7] = ss[r];
    }
    __syncthreads();

    // 64 rows x 12 pairs = 768 columns; 3 per thread
#pragma unroll
    for (int jj = 0; jj < 3; jj++) {
        int col = jj * NTHREADS + tid;
        int p = col >> 6, rl = col & 63;  // lanes consecutive in rl -> coalesced
        float sx = 0.f, sy = 0.f;
#pragma unroll
        for (int t = 0; t < 8; t++) {
            float2 a = red[((size_t)rl * 8 + t) * PPAD + p];
            sx += a.x;
            sy += a.y;
        }
        g_hpart[bk][p][row0 + rl] = make_float2(sx, sy);
    }
    if (tid < MB) {
        float s = 0.f;
#pragma unroll
        for (int t = 0; t < 8; t++) s += ssred[tid * 8 + t];
        g_sspart[bk][row0 + tid] = s;
    }
}

// ---------------------------------------------------------------------------
// Kernel B (known-good R4 form): 1 row/thread, grid 128 x 32.
// rcp.approx only; convergence checked every 8 iterations via
// multiply-compare. Cap 400 = reference MAX_IT^2.
// ---------------------------------------------------------------------------
extern "C" __global__ void __launch_bounds__(32)
mhc_finish_kernel(const float* __restrict__ bias, const float* __restrict__ alpha,
                  float* __restrict__ out) {
    int row = blockIdx.x * 32 + threadIdx.x;

    float h[N_OUT];
#pragma unroll
    for (int p = 0; p < NP; p++) {
        float sx = 0.f, sy = 0.f;
#pragma unroll
        for (int c = 0; c < KSPLIT; c++) {
            float2 a = g_hpart[c][p][row];
            sx += a.x;
            sy += a.y;
        }
        h[2 * p] = sx;
        h[2 * p + 1] = sy;
    }
    float ss = 0.f;
#pragma unroll
    for (int c = 0; c < KSPLIT; c++) ss += g_sspart[c][row];

    float r_inv = rsqrtf(ss * (1.0f / K_DIM));
    float a0 = alpha[0], a1 = alpha[1], a2 = alpha[2];

    float pre[HCN], post[HCN], H[HCN][HCN];
#pragma unroll
    for (int n = 0; n < HCN; n++) {
        float z0 = fmaf(r_inv * a0, h[n], bias[n]);
        pre[n] = 1.f / (1.f + __expf(-z0));
        float z1 = fmaf(r_inv * a1, h[HCN + n], bias[HCN + n]);
        post[n] = 2.f / (1.f + __expf(-z1));
    }
#pragma unroll
    for (int i = 0; i < HCN; i++)
#pragma unroll
        for (int j = 0; j < HCN; j++) {
            float z = fmaf(r_inv * a2, h[8 + 4 * i + j], bias[8 + 4 * i + j]);
            H[i][j] = __expf(z);
        }

    const float EPSV = 1e-12f;
    float u[4] = {1.f, 1.f, 1.f, 1.f}, v[4] = {1.f, 1.f, 1.f, 1.f};
    for (int o = 0; o < 50; o++) {          // 50 blocks x 8 iters = 400 max
        float vp0 = v[0], vp1 = v[1], vp2 = v[2], vp3 = v[3];
#pragma unroll
        for (int s = 0; s < 8; s++) {
            float nu[4];
#pragma unroll
            for (int i = 0; i < 4; i++) {
                float uv = fmaf(H[i][3], v[3],
                           fmaf(H[i][2], v[2],
                           fmaf(H[i][1], v[1],
                           fmaf(H[i][0], v[0], EPSV))));
                nu[i] = frcp(uv);
            }
#pragma unroll
            for (int j = 0; j < 4; j++) {
                float vu = fmaf(H[3][j], nu[3],
                           fmaf(H[2][j], nu[2],
                           fmaf(H[1][j], nu[1],
                           fmaf(H[0][j], nu[0], EPSV))));
                v[j] = frcp(vu);
            }
            u[0] = nu[0]; u[1] = nu[1]; u[2] = nu[2]; u[3] = nu[3];
        }
        float m = fabsf(v[0] - vp0) - 1e-6f * fabsf(v[0]);
        m = fmaxf(m, fabsf(v[1] - vp1) - 1e-6f * fabsf(v[1]));
        m = fmaxf(m, fabsf(v[2] - vp2) - 1e-6f * fabsf(v[2]));
        m = fmaxf(m, fabsf(v[3] - vp3) - 1e-6f * fabsf(v[3]));
        if (m <= 0.f) break;
    }

    ((float4*)out)[row] = make_float4(pre[0], pre[1], pre[2], pre[3]);
    ((float4*)(out + (size_t)T_DIM * HCN))[row] =
        make_float4(post[0], post[1], post[2], post[3]);
    float4* res = (float4*)(out + 2 * (size_t)T_DIM * HCN + (size_t)row * 16);
#pragma unroll
    for (int i = 0; i < 4; i++) {
        res[i] = make_float4(u[i] * H[i][0] * v[0], u[i] * H[i][1] * v[1],
                             u[i] * H[i][2] * v[2], u[i] * H[i][3] * v[3]);
    }
}

// ---------------------------------------------------------------------------
extern "C" void kernel_launch(void* const* d_in, const int* in_sizes, int n_in,
                              void* d_out, int out_size) {
    const float* x = (const float*)d_in[0];
    const float* w = (const float*)d_in[1];
    const float* bias = (const float*)d_in[2];
    const float* alpha = (const float*)d_in[3];
    float* out = (float*)d_out;

    cudaFuncSetAttribute(mhc_gemm_kernel,
                         cudaFuncAttributeMaxDynamicSharedMemorySize,
                         SMEM_BYTES);

    dim3 grid(T_DIM / MB, KSPLIT);
    mhc_gemm_kernel<<<grid, NTHREADS, SMEM_BYTES>>>(x, w);
    mhc_finish_kernel<<<T_DIM / 32, 32>>>(bias, alpha, out);
}

// round 10
// speedup vs baseline: 2.5146x; 1.0567x over previous
#include <cuda_runtime.h>
#include <cstdint>

#define T_DIM 4096
#define K_DIM 16384
#define HCN 4
#define N_OUT 24
#define NP 12          // float2 pairs across N
#define MB 64          // rows per CTA (8 warps x RT)
#define KSPLIT 8
#define KCHUNK (K_DIM / KSPLIT)   // 2048
#define KT 512         // weight K tile staged in smem
#define NTILES (KCHUNK / KT)      // 4
#define RT 8           // rows per warp
#define NTHREADS 256
#define PSTRIDE 524    // u64 stride per pair in smem (524%16=12 -> conflict-free)
#define PPAD 13        // padded pair stride for reduction

#define STAGE_K 64                 // k per x pipeline stage
#define NSTG (KCHUNK / STAGE_K)    // 32 stages per chunk
#define NSLOTS 3                   // x smem slots (2 in flight)
#define XSLOT_BYTES (MB * STAGE_K * 4)        // 16384
#define WBYTES (NP * PSTRIDE * 8)             // 50304
#define SMEM_BYTES (WBYTES + NSLOTS * XSLOT_BYTES)  // 99456 (2 CTAs/SM fit)

// Scratch (device globals). Transposed [split][pair][row] for coalesced reads.
__device__ float2 g_hpart[KSPLIT][NP][T_DIM];
__device__ float  g_sspart[KSPLIT][T_DIM];

using u64 = unsigned long long;

__device__ __forceinline__ u64 fma2(u64 a, u64 b, u64 c) {
    u64 d;
    asm("fma.rn.f32x2 %0, %1, %2, %3;" : "=l"(d) : "l"(a), "l"(b), "l"(c));
    return d;
}
__device__ __forceinline__ u64 pack2(float x) {
    u64 d;
    asm("mov.b64 %0, {%1, %1};" : "=l"(d) : "f"(x));
    return d;
}
__device__ __forceinline__ float2 u2f(u64 a) {
    float2 f;
    asm("mov.b64 {%0, %1}, %2;" : "=f"(f.x), "=f"(f.y) : "l"(a));
    return f;
}
__device__ __forceinline__ float frcp(float a) {
    float r;
    asm("rcp.approx.f32 %0, %1;" : "=f"(r) : "f"(a));
    return r;
}
__device__ __forceinline__ float f4get(const float4& v, int s) {
    return s == 0 ? v.x : (s == 1 ? v.y : (s == 2 ? v.z : v.w));
}
__device__ __forceinline__ void cp_async16(uint32_t dst_smem, const void* src) {
    asm volatile("cp.async.cg.shared.global [%0], [%1], 16;"
                 :: "r"(dst_smem), "l"(src));
}
__device__ __forceinline__ void cp_commit() {
    asm volatile("cp.async.commit_group;");
}
template <int N>
__device__ __forceinline__ void cp_wait() {
    asm volatile("cp.async.wait_group %0;" :: "n"(N));
}

// ---------------------------------------------------------------------------
// Kernel A — quarter-split + cp.async pipeline + 2 CTAs/SM + rotated rows.
// Warp: lane = g*8 + l7; group g owns output pairs [3g,3g+3); l7 = k lane.
// Row rotation: thread (g,l7) accumulator j corresponds to warp row
// (j + 2g) & 7. Hence local rows 0,1 are globally rows 2g, 2g+1 — each group
// computes ss for exactly its 2 rows (2 fmaf/s-step instead of 8, statically
// indexed). x LDS.128 stays conflict-free: each 8-lane phase group reads one
// row's contiguous 128B regardless of rotation.
// ---------------------------------------------------------------------------
extern "C" __global__ void __launch_bounds__(NTHREADS, 2)
mhc_gemm_kernel(const float* __restrict__ x, const float* __restrict__ w) {
    extern __shared__ char smem[];
    u64* sw = (u64*)smem;  // weights: [12 pairs][PSTRIDE u64]
    const uint32_t smem_u32 = (uint32_t)__cvta_generic_to_shared(smem);
    const uint32_t xbase = smem_u32 + WBYTES;

    const int tid = threadIdx.x;
    const int wid = tid >> 5;          // warp 0..7
    const int g   = (tid >> 3) & 3;    // pair group 0..3
    const int l7  = tid & 7;           // k lane 0..7
    const int p3  = g * 3;
    const int bm = blockIdx.x;
    const int bk = blockIdx.y;
    const int row0 = bm * MB;

    // x fill mapping: thread t copies 4x16B for row = t>>2, quarter q = t&3
    const int frow = tid >> 2, fq = tid & 3;
    const float* fsrc_base =
        x + (size_t)(row0 + frow) * K_DIM + bk * KCHUNK + fq * 16;
    const uint32_t fdst_base = xbase + (uint32_t)(frow * (STAGE_K * 4) + fq * 64);

    // Per-thread rotated row byte offsets within an x slot (row stride 256B)
    uint32_t rowoff[RT];
#pragma unroll
    for (int r = 0; r < RT; r++)
        rowoff[r] = (uint32_t)((wid * RT + ((r + 2 * g) & 7)) * (STAGE_K * 4));

    u64 acc[RT][3];
    float ssa = 0.f, ssb = 0.f;   // ss for warp rows 2g, 2g+1 (local 0,1)
#pragma unroll
    for (int r = 0; r < RT; r++)
#pragma unroll
        for (int j = 0; j < 3; j++) acc[r][j] = 0ull;

    // Prologue: fill stages 0,1
#pragma unroll
    for (int st = 0; st < NSLOTS - 1; st++) {
        const float* src = fsrc_base + st * STAGE_K;
        uint32_t dst = fdst_base + st * XSLOT_BYTES;
#pragma unroll
        for (int i = 0; i < 4; i++)
            cp_async16(dst + i * 16, src + i * 4);
        cp_commit();
    }

    int slot = 0;   // st % NSLOTS, tracked incrementally
    for (int tile = 0; tile < NTILES; tile++) {
        const int k0 = bk * KCHUNK + tile * KT;

        __syncthreads();   // prev tile's compute done before restaging weights
        // Stage W[k0..k0+KT)[0:24) -> sw[p][(k&3)*128 + (k>>2)]
#pragma unroll
        for (int it = 0; it < (KT * 6) / NTHREADS; it++) {
            int idx = tid + NTHREADS * it;
            int kk = idx / 6, q = idx % 6;
            float4 v = *(const float4*)(w + (size_t)(k0 + kk) * N_OUT + q * 4);
            int base = (kk & 3) * 128 + (kk >> 2);
            ((float2*)sw)[(2 * q + 0) * PSTRIDE + base] = make_float2(v.x, v.y);
            ((float2*)sw)[(2 * q + 1) * PSTRIDE + base] = make_float2(v.z, v.w);
        }

        for (int j = 0; j < KT / STAGE_K; j++) {   // 8 x-stages per weight tile
            const int st = tile * (KT / STAGE_K) + j;

            cp_wait<1>();        // stage st landed (st+1 may be in flight)
            __syncthreads();     // data visible; prev-iter consumers done

            const char* xs = smem + WBYTES + slot * XSLOT_BYTES;
#pragma unroll
            for (int bi = 0; bi < 2; bi++) {
                float4 xv[RT];
#pragma unroll
                for (int r = 0; r < RT; r++)
                    xv[r] = *(const float4*)(xs + rowoff[r] + ((bi * 8 + l7) << 4));
                const int kf4 = j * 16 + bi * 8 + l7;  // within weight tile
#pragma unroll
                for (int s = 0; s < 4; s++) {
                    u64 wp[3];
#pragma unroll
                    for (int jj = 0; jj < 3; jj++)
                        wp[jj] = sw[(p3 + jj) * PSTRIDE + s * 128 + kf4];
#pragma unroll
                    for (int r = 0; r < RT; r++) {
                        float xsv = f4get(xv[r], s);
                        u64 X = pack2(xsv);
#pragma unroll
                        for (int jj = 0; jj < 3; jj++)
                            acc[r][jj] = fma2(X, wp[jj], acc[r][jj]);
                    }
                    // ss only for this group's two rows (local 0,1)
                    float xa = f4get(xv[0], s), xb = f4get(xv[1], s);
                    ssa = fmaf(xa, xa, ssa);
                    ssb = fmaf(xb, xb, ssb);
                }
            }

            // Refill stage st+2 into slot (st+2)%3 (consumed at iter st-1)
            if (st + NSLOTS - 1 < NSTG) {
                const float* src = fsrc_base + (st + NSLOTS - 1) * STAGE_K;
                int rslot = slot + 2;
                if (rslot >= NSLOTS) rslot -= NSLOTS;
                uint32_t dst = fdst_base + rslot * XSLOT_BYTES;
#pragma unroll
                for (int i = 0; i < 4; i++)
                    cp_async16(dst + i * 16, src + i * 4);
            }
            cp_commit();   // keep group count aligned with stage index
            if (++slot == NSLOTS) slot = 0;
        }
    }

    cp_wait<0>();
    __syncthreads();

    // Cross-k-lane reduction via smem (overlays weight buffer + x slots).
    float2* red = (float2*)smem;                                 // [64][8][PPAD]
    float* ssred = (float*)(smem + (size_t)MB * 8 * PPAD * 8);   // [64][8]
#pragma unroll
    for (int r = 0; r < RT; r++) {
        int rl = wid * RT + ((r + 2 * g) & 7);   // rotated row
#pragma unroll
        for (int jj = 0; jj < 3; jj++)
            red[((size_t)rl * 8 + l7) * PPAD + p3 + jj] = u2f(acc[r][jj]);
    }
    {
        int rl0 = wid * RT + 2 * g;
        ssred[(rl0 + 0) * 8 + l7] = ssa;
        ssred[(rl0 + 1) * 8 + l7] = ssb;
    }
    __syncthreads();

    // 64 rows x 12 pairs = 768 columns; 3 per thread
#pragma unroll
    for (int jj = 0; jj < 3; jj++) {
        int col = jj * NTHREADS + tid;
        int p = col >> 6, rl = col & 63;  // lanes consecutive in rl -> coalesced
        float sx = 0.f, sy = 0.f;
#pragma unroll
        for (int t = 0; t < 8; t++) {
            float2 a = red[((size_t)rl * 8 + t) * PPAD + p];
            sx += a.x;
            sy += a.y;
        }
        g_hpart[bk][p][row0 + rl] = make_float2(sx, sy);
    }
    if (tid < MB) {
        float s = 0.f;
#pragma unroll
        for (int t = 0; t < 8; t++) s += ssred[tid * 8 + t];
        g_sspart[bk][row0 + tid] = s;
    }
}

// ---------------------------------------------------------------------------
// Kernel B (known-good R4 form): 1 row/thread, grid 128 x 32.
// rcp.approx only; convergence checked every 8 iterations via
// multiply-compare. Cap 400 = reference MAX_IT^2.
// ---------------------------------------------------------------------------
extern "C" __global__ void __launch_bounds__(32)
mhc_finish_kernel(const float* __restrict__ bias, const float* __restrict__ alpha,
                  float* __restrict__ out) {
    int row = blockIdx.x * 32 + threadIdx.x;

    float h[N_OUT];
#pragma unroll
    for (int p = 0; p < NP; p++) {
        float sx = 0.f, sy = 0.f;
#pragma unroll
        for (int c = 0; c < KSPLIT; c++) {
            float2 a = g_hpart[c][p][row];
            sx += a.x;
            sy += a.y;
        }
        h[2 * p] = sx;
        h[2 * p + 1] = sy;
    }
    float ss = 0.f;
#pragma unroll
    for (int c = 0; c < KSPLIT; c++) ss += g_sspart[c][row];

    float r_inv = rsqrtf(ss * (1.0f / K_DIM));
    float a0 = alpha[0], a1 = alpha[1], a2 = alpha[2];

    float pre[HCN], post[HCN], H[HCN][HCN];
#pragma unroll
    for (int n = 0; n < HCN; n++) {
        float z0 = fmaf(r_inv * a0, h[n], bias[n]);
        pre[n] = 1.f / (1.f + __expf(-z0));
        float z1 = fmaf(r_inv * a1, h[HCN + n], bias[HCN + n]);
        post[n] = 2.f / (1.f + __expf(-z1));
    }
#pragma unroll
    for (int i = 0; i < HCN; i++)
#pragma unroll
        for (int j = 0; j < HCN; j++) {
            float z = fmaf(r_inv * a2, h[8 + 4 * i + j], bias[8 + 4 * i + j]);
            H[i][j] = __expf(z);
        }

    const float EPSV = 1e-12f;
    float u[4] = {1.f, 1.f, 1.f, 1.f}, v[4] = {1.f, 1.f, 1.f, 1.f};
    for (int o = 0; o < 50; o++) {          // 50 blocks x 8 iters = 400 max
        float vp0 = v[0], vp1 = v[1], vp2 = v[2], vp3 = v[3];
#pragma unroll
        for (int s = 0; s < 8; s++) {
            float nu[4];
#pragma unroll
            for (int i = 0; i < 4; i++) {
                float uv = fmaf(H[i][3], v[3],
                           fmaf(H[i][2], v[2],
                           fmaf(H[i][1], v[1],
                           fmaf(H[i][0], v[0], EPSV))));
                nu[i] = frcp(uv);
            }
#pragma unroll
            for (int j = 0; j < 4; j++) {
                float vu = fmaf(H[3][j], nu[3],
                           fmaf(H[2][j], nu[2],
                           fmaf(H[1][j], nu[1],
                           fmaf(H[0][j], nu[0], EPSV))));
                v[j] = frcp(vu);
            }
            u[0] = nu[0]; u[1] = nu[1]; u[2] = nu[2]; u[3] = nu[3];
        }
        float m = fabsf(v[0] - vp0) - 1e-6f * fabsf(v[0]);
        m = fmaxf(m, fabsf(v[1] - vp1) - 1e-6f * fabsf(v[1]));
        m = fmaxf(m, fabsf(v[2] - vp2) - 1e-6f * fabsf(v[2]));
        m = fmaxf(m, fabsf(v[3] - vp3) - 1e-6f * fabsf(v[3]));
        if (m <= 0.f) break;
    }

    ((float4*)out)[row] = make_float4(pre[0], pre[1], pre[2], pre[3]);
    ((float4*)(out + (size_t)T_DIM * HCN))[row] =
        make_float4(post[0], post[1], post[2], post[3]);
    float4* res = (float4*)(out + 2 * (size_t)T_DIM * HCN + (size_t)row * 16);
#pragma unroll
    for (int i = 0; i < 4; i++) {
        res[i] = make_float4(u[i] * H[i][0] * v[0], u[i] * H[i][1] * v[1],
                             u[i] * H[i][2] * v[2], u[i] * H[i][3] * v[3]);
    }
}

// ---------------------------------------------------------------------------
extern "C" void kernel_launch(void* const* d_in, const int* in_sizes, int n_in,
                              void* d_out, int out_size) {
    const float* x = (const float*)d_in[0];
    const float* w = (const float*)d_in[1];
    const float* bias = (const float*)d_in[2];
    const float* alpha = (const float*)d_in[3];
    float* out = (float*)d_out;

    cudaFuncSetAttribute(mhc_gemm_kernel,
                         cudaFuncAttributeMaxDynamicSharedMemorySize,
                         SMEM_BYTES);

    dim3 grid(T_DIM / MB, KSPLIT);
    mhc_gemm_kernel<<<grid, NTHREADS, SMEM_BYTES>>>(x, w);
    mhc_finish_kernel<<<T_DIM / 32, 32>>>(bias, alpha, out);
}